// round 5
// baseline (speedup 1.0000x reference)
#include <cuda_runtime.h>
#include <cstdint>

#define TABLE_SIZE 524288u          // 2^19 -> modulo is a mask
#define NUM_LEVELS 16
#define N_POINTS (1u << 20)
#define HASH_PRIME 2654435761u

#define BLOCK 256
#define N_PAIR_THREADS (N_POINTS * 8u)   // thread = (point, j), j=0..7 -> levels j, j+8

// scalings: floor(16 * (2^0.4)^l) in fp32, matching the reference exactly.
__constant__ float kScale[NUM_LEVELS] = {
    16.0f, 21.0f, 27.0f, 36.0f, 48.0f, 64.0f, 84.0f, 111.0f,
    147.0f, 194.0f, 256.0f, 337.0f, 445.0f, 588.0f, 776.0f, 1024.0f
};

__device__ __forceinline__ void corners(float sx, float sy,
                                        uint32_t& fx, uint32_t& fy,
                                        uint32_t& cx, uint32_t& cy,
                                        float& ox, float& oy)
{
    const float fxf = floorf(sx);
    const float fyf = floorf(sy);
    fx = (uint32_t)(int32_t)fxf;
    fy = (uint32_t)(int32_t)fyf;
    cx = (uint32_t)(int32_t)ceilf(sx);
    cy = (uint32_t)(int32_t)ceilf(sy);
    ox = sx - fxf;
    oy = sy - fyf;
}

__device__ __forceinline__ float2 lerp2(float2 f0, float2 f1, float2 f2, float2 f3,
                                        float ox, float oy)
{
    const float omx = 1.0f - ox;
    const float omy = 1.0f - oy;
    float2 e;
    e.x = (f0.x * ox + f3.x * omx) * oy + (f1.x * ox + f2.x * omx) * omy;
    e.y = (f0.y * ox + f3.y * omx) * oy + (f1.y * ox + f2.y * omx) * omy;
    return e;
}

__global__ __launch_bounds__(BLOCK)
void hash_encode_kernel(const float2* __restrict__ x,
                        const float2* __restrict__ table,
                        float2* __restrict__ out)
{
    const uint32_t t = blockIdx.x * BLOCK + threadIdx.x;
    if (t >= N_PAIR_THREADS) return;

    const uint32_t p = t >> 3;          // point
    const uint32_t j = t & 7u;          // hot level j (0..7), cold level j+8

    const float2 xp = __ldg(&x[p]);     // 8 lanes broadcast same point

    // ---------------- hot level j: L1-cached gathers ----------------
    {
        const float s  = kScale[j];
        uint32_t fx, fy, cx, cy; float ox, oy;
        corners(xp.x * s, xp.y * s, fx, fy, cx, cy, ox, oy);

        const uint32_t base = j * TABLE_SIZE;
        const uint32_t hyc  = cy * HASH_PRIME;
        const uint32_t hyf  = fy * HASH_PRIME;
        const uint32_t h0 = ((cx ^ hyc) & (TABLE_SIZE - 1u)) + base;
        const uint32_t h1 = ((cx ^ hyf) & (TABLE_SIZE - 1u)) + base;
        const uint32_t h2 = ((fx ^ hyc) & (TABLE_SIZE - 1u)) + base;
        const uint32_t h3 = ((fx ^ hyf) & (TABLE_SIZE - 1u)) + base;

        const float2 f0 = __ldg(&table[h0]);
        const float2 f1 = __ldg(&table[h1]);
        const float2 f2 = __ldg(&table[h2]);
        const float2 f3 = __ldg(&table[h3]);

        out[(p << 4) + j] = lerp2(f0, f1, f2, f3, ox, oy);
    }

    // ------------- cold level j+8: L2-only gathers (.cg) -------------
    {
        const uint32_t l = j + 8u;
        const float s  = kScale[l];
        uint32_t fx, fy, cx, cy; float ox, oy;
        corners(xp.x * s, xp.y * s, fx, fy, cx, cy, ox, oy);

        const uint32_t base = l * TABLE_SIZE;
        const uint32_t hyc  = cy * HASH_PRIME;
        const uint32_t hyf  = fy * HASH_PRIME;
        const uint32_t h0 = ((cx ^ hyc) & (TABLE_SIZE - 1u)) + base;
        const uint32_t h1 = ((cx ^ hyf) & (TABLE_SIZE - 1u)) + base;
        const uint32_t h2 = ((fx ^ hyc) & (TABLE_SIZE - 1u)) + base;
        const uint32_t h3 = ((fx ^ hyf) & (TABLE_SIZE - 1u)) + base;

        const float2 f0 = __ldcg(&table[h0]);
        const float2 f1 = __ldcg(&table[h1]);
        const float2 f2 = __ldcg(&table[h2]);
        const float2 f3 = __ldcg(&table[h3]);

        out[(p << 4) + l] = lerp2(f0, f1, f2, f3, ox, oy);
    }
}

extern "C" void kernel_launch(void* const* d_in, const int* in_sizes, int n_in,
                              void* d_out, int out_size)
{
    const float2* x     = (const float2*)d_in[0];   // (N_POINTS, 2) float32
    const float2* table = (const float2*)d_in[1];   // (TABLE_SIZE*16, 2) float32
    float2* out = (float2*)d_out;                   // (N_POINTS, 32) float32

    const uint32_t grid = (N_PAIR_THREADS + BLOCK - 1) / BLOCK;   // 32768
    hash_encode_kernel<<<grid, BLOCK>>>(x, table, out);
}